// round 15
// baseline (speedup 1.0000x reference)
#include <cuda_runtime.h>
#include <cuda_bf16.h>
#include <math.h>
#include <float.h>
#include <stdint.h>

// Problem constants (match reference)
#define NN 100000
#define NE 1600000
#define NF 128
#define NL 7
#define SLOPE 0.02f
#define CAP 64            // bucket capacity per node; P(deg>64)~1e-18 for Poisson(16)

// ---------------- device scratch (static, no allocation) ----------------
// g_counts zero-init at load; aggout re-zeroes it at the end of every call.
__device__ int g_counts[NN];
__device__ int g_col[NN * CAP];
__device__ __align__(16) float g_h0[NN * NF];
__device__ __align__(16) float g_h1[NN * NF];
__device__ __align__(16) float g_partial[NN * NF];
__device__ __align__(16) uint32_t g_aggP[NN * NF];   // packed (bf16hi<<16)|bf16lo
// pre-split weights: hi/lo bf16, layout [l][n][k]
__device__ __align__(16) uint16_t g_WlHi[NL * NF * NF];
__device__ __align__(16) uint16_t g_WlLo[NL * NF * NF];
__device__ __align__(16) uint16_t g_WrHi[NL * NF * NF];
__device__ __align__(16) uint16_t g_WrLo[NL * NF * NF];

// ---------------- bucket CSR fill + weight pre-split (single launch) ----------------
__global__ void fill_kernel(const int* __restrict__ src, const int* __restrict__ dst,
                            const float* __restrict__ Wl, const float* __restrict__ Wr) {
    int e = blockIdx.x * blockDim.x + threadIdx.x;
    if (e < NE) {
        int d = dst[e];
        int off = atomicAdd(&g_counts[d], 1);
        g_col[d * CAP + off] = src[e];
    }
    if (e < NL * NF * NF) {
        float a = Wl[e];
        __nv_bfloat16 h = __float2bfloat16(a);
        g_WlHi[e] = __bfloat16_as_ushort(h);
        g_WlLo[e] = __bfloat16_as_ushort(__float2bfloat16(a - __bfloat162float(h)));
        float b = Wr[e];
        __nv_bfloat16 hb = __float2bfloat16(b);
        g_WrHi[e] = __bfloat16_as_ushort(hb);
        g_WrLo[e] = __bfloat16_as_ushort(__float2bfloat16(b - __bfloat162float(hb)));
    }
}

// ---------------- helpers ----------------
__device__ __forceinline__ float4 fmax4(float4 a, float4 b) {
    a.x = fmaxf(a.x, b.x); a.y = fmaxf(a.y, b.y);
    a.z = fmaxf(a.z, b.z); a.w = fmaxf(a.w, b.w);
    return a;
}

__device__ __forceinline__ uint32_t smem_u32(const void* p) {
    uint32_t a;
    asm("{ .reg .u64 t; cvta.to.shared.u64 t, %1; cvt.u32.u64 %0, t; }" : "=r"(a) : "l"(p));
    return a;
}

__device__ __forceinline__ void ldm4(uint32_t* r, uint32_t addr) {
    asm volatile("ldmatrix.sync.aligned.m8n8.x4.shared.b16 {%0,%1,%2,%3}, [%4];"
                 : "=r"(r[0]), "=r"(r[1]), "=r"(r[2]), "=r"(r[3]) : "r"(addr));
}

__device__ __forceinline__ void mma_bf16(float* d, const uint32_t* a, uint32_t b0, uint32_t b1) {
    asm volatile(
        "mma.sync.aligned.m16n8k16.row.col.f32.bf16.bf16.f32 "
        "{%0,%1,%2,%3}, {%4,%5,%6,%7}, {%8,%9}, {%0,%1,%2,%3};"
        : "+f"(d[0]), "+f"(d[1]), "+f"(d[2]), "+f"(d[3])
        : "r"(a[0]), "r"(a[1]), "r"(a[2]), "r"(a[3]), "r"(b0), "r"(b1));
}

__device__ __forceinline__ void cp16(uint32_t d, const void* s) {
    asm volatile("cp.async.cg.shared.global [%0], [%1], 16;" :: "r"(d), "l"(s));
}

// pack fp32 -> (bf16hi<<16)|bf16lo
__device__ __forceinline__ uint32_t pack1(float v) {
    __nv_bfloat16 h = __float2bfloat16(v);
    __nv_bfloat16 l = __float2bfloat16(v - __bfloat162float(h));
    return ((uint32_t)__bfloat16_as_ushort(h) << 16) | __bfloat16_as_ushort(l);
}

// ---------------- max aggregation: fp32 gather from buckets, packed output ----------------
__global__ __launch_bounds__(256) void agg_kernel(const float* __restrict__ h,
                                                  uint32_t* __restrict__ aggP) {
    int warp = (blockIdx.x * blockDim.x + threadIdx.x) >> 5;
    int lane = threadIdx.x & 31;
    if (warp >= NN) return;
    int cnt = g_counts[warp];
    const int* col = &g_col[warp * CAP];
    const float4* h4 = (const float4*)h;
    float4 m = make_float4(-FLT_MAX, -FLT_MAX, -FLT_MAX, -FLT_MAX);
    int e = 0;
    for (; e + 8 <= cnt; e += 8) {
        float4 v0 = h4[col[e]     * 32 + lane];
        float4 v1 = h4[col[e + 1] * 32 + lane];
        float4 v2 = h4[col[e + 2] * 32 + lane];
        float4 v3 = h4[col[e + 3] * 32 + lane];
        float4 v4 = h4[col[e + 4] * 32 + lane];
        float4 v5 = h4[col[e + 5] * 32 + lane];
        float4 v6 = h4[col[e + 6] * 32 + lane];
        float4 v7 = h4[col[e + 7] * 32 + lane];
        m = fmax4(m, fmax4(fmax4(fmax4(v0, v1), fmax4(v2, v3)),
                           fmax4(fmax4(v4, v5), fmax4(v6, v7))));
    }
    for (; e < cnt; e++) m = fmax4(m, h4[col[e] * 32 + lane]);
    if (cnt == 0) m = make_float4(0.f, 0.f, 0.f, 0.f);
    uint4 pk = make_uint4(pack1(m.x), pack1(m.y), pack1(m.z), pack1(m.w));
    ((uint4*)aggP)[warp * 32 + lane] = pk;
}

// ================= half-GEMM kernels (M=64, bf16x3, 1 barrier each) =================
#define A_STRIDE 272
#define SA_HI   0
#define SA_LO   17408
#define SW_BASE 34816
#define SW_BUF  34816
#define SM_TOT  104448

__device__ __forceinline__ void stage_w_async(uint32_t su,
    const uint16_t* __restrict__ WHi, const uint16_t* __restrict__ WLo,
    int nbase, int buf, int tid)
{
    uint32_t base = su + SW_BASE + buf * SW_BUF;
#pragma unroll
    for (int i = 0; i < 8; i++) {
        int idx = tid + i * 256;
        int plane = idx >> 10;
        int rem = idx & 1023;
        int nl = rem >> 4;
        int q  = rem & 15;
        uint32_t dst = base + plane * 17408 + nl * A_STRIDE + q * 16;
        const uint16_t* s = (plane ? WLo : WHi) + (size_t)(nbase + nl) * NF + q * 8;
        cp16(dst, s);
    }
    asm volatile("cp.async.commit_group;" ::: "memory");
}

// stage 64 A-rows from packed source: LDG + PRMT only
__device__ __forceinline__ void stage_A_packed(char* smem, const uint32_t* __restrict__ src,
                                               int rowBase, int M, int tid) {
    const uint4* s4 = (const uint4*)src;
#pragma unroll
    for (int i = 0; i < 8; i++) {
        int idx = tid + i * 256;
        int row = idx >> 5;
        int q   = idx & 31;
        int gm  = rowBase + row;
        uint4 p = make_uint4(0, 0, 0, 0);
        if (gm < M) p = s4[gm * 32 + q];
        uint32_t hi01 = __byte_perm(p.x, p.y, 0x7632);
        uint32_t lo01 = __byte_perm(p.x, p.y, 0x5410);
        uint32_t hi23 = __byte_perm(p.z, p.w, 0x7632);
        uint32_t lo23 = __byte_perm(p.z, p.w, 0x5410);
        uint32_t off = (uint32_t)(row * A_STRIDE + q * 8);
        *(uint2*)(smem + SA_HI + off) = make_uint2(hi01, hi23);
        *(uint2*)(smem + SA_LO + off) = make_uint2(lo01, lo23);
    }
}

// stage 64 A-rows from fp32 source (cvt path)
__device__ __forceinline__ void stage_A_f32(char* smem, const float* __restrict__ src,
                                            int rowBase, int M, int tid) {
    const float4* s4 = (const float4*)src;
#pragma unroll
    for (int i = 0; i < 8; i++) {
        int idx = tid + i * 256;
        int row = idx >> 5;
        int q   = idx & 31;
        int gm  = rowBase + row;
        float4 v = make_float4(0.f, 0.f, 0.f, 0.f);
        if (gm < M) v = s4[gm * 32 + q];
        __nv_bfloat16 hx = __float2bfloat16(v.x);
        __nv_bfloat16 hy = __float2bfloat16(v.y);
        __nv_bfloat16 hz = __float2bfloat16(v.z);
        __nv_bfloat16 hw = __float2bfloat16(v.w);
        uint32_t hi01 = ((uint32_t)__bfloat16_as_ushort(hy) << 16) | __bfloat16_as_ushort(hx);
        uint32_t hi23 = ((uint32_t)__bfloat16_as_ushort(hw) << 16) | __bfloat16_as_ushort(hz);
        __nv_bfloat16 lx = __float2bfloat16(v.x - __bfloat162float(hx));
        __nv_bfloat16 ly = __float2bfloat16(v.y - __bfloat162float(hy));
        __nv_bfloat16 lz = __float2bfloat16(v.z - __bfloat162float(hz));
        __nv_bfloat16 lw = __float2bfloat16(v.w - __bfloat162float(hw));
        uint32_t lo01 = ((uint32_t)__bfloat16_as_ushort(ly) << 16) | __bfloat16_as_ushort(lx);
        uint32_t lo23 = ((uint32_t)__bfloat16_as_ushort(lw) << 16) | __bfloat16_as_ushort(lz);
        uint32_t off = (uint32_t)(row * A_STRIDE + q * 8);
        *(uint2*)(smem + SA_HI + off) = make_uint2(hi01, hi23);
        *(uint2*)(smem + SA_LO + off) = make_uint2(lo01, lo23);
    }
}

// K=128 sweep over one 64-col chunk; interleaved emission
__device__ __forceinline__ void mma_chunk(float acc[][4], int accBase,
                                          uint32_t aHiB, uint32_t aLoB,
                                          uint32_t bHiB, uint32_t bLoB) {
#pragma unroll
    for (int ks = 0; ks < 8; ks++) {
        uint32_t ko = ks * 32;
        uint32_t ah[4], al[4];
        ldm4(ah, aHiB + ko);
        ldm4(al, aLoB + ko);
#pragma unroll
        for (int p = 0; p < 2; p++) {
            uint32_t bh[4], blx[4];
            uint32_t po = (uint32_t)(p * 16 * A_STRIDE) + ko;
            ldm4(bh,  bHiB + po);
            ldm4(blx, bLoB + po);
            float* d0 = acc[accBase + p * 2];
            float* d1 = acc[accBase + p * 2 + 1];
            mma_bf16(d0, ah, bh[0],  bh[1]);
            mma_bf16(d1, ah, bh[2],  bh[3]);
            mma_bf16(d0, ah, blx[0], blx[1]);
            mma_bf16(d1, ah, blx[2], blx[3]);
            mma_bf16(d0, al, bh[0],  bh[1]);
            mma_bf16(d1, al, bh[2],  bh[3]);
        }
    }
}

// partial = h @ Wr^T (no bias/activation); 1 barrier
__global__ __launch_bounds__(256, 2) void gemmWr_kernel(
    const float* __restrict__ h,
    const uint16_t* __restrict__ WrHi, const uint16_t* __restrict__ WrLo,
    float* __restrict__ P, int M)
{
    extern __shared__ char smem[];
    uint32_t su = smem_u32(smem);
    int tid = threadIdx.x, lane = tid & 31, wid = tid >> 5;
    int wm = wid & 3, wn = wid >> 2;
    int rowBase = blockIdx.x * 64;

    int lr = lane & 7, g = lane >> 3;
    uint32_t aOff = (uint32_t)((wm * 16 + lr + (g & 1) * 8) * A_STRIDE + (g >> 1) * 16);
    uint32_t bOff = (uint32_t)((wn * 32 + lr + (g >> 1) * 8) * A_STRIDE + (g & 1) * 16);
    uint32_t aHiB = su + SA_HI + aOff, aLoB = su + SA_LO + aOff;
    uint32_t w0Hi = su + SW_BASE + bOff,          w0Lo = w0Hi + 17408;
    uint32_t w1Hi = su + SW_BASE + SW_BUF + bOff, w1Lo = w1Hi + 17408;

    float acc[8][4];
#pragma unroll
    for (int i = 0; i < 8; i++)
#pragma unroll
        for (int q = 0; q < 4; q++) acc[i][q] = 0.f;

    stage_w_async(su, WrHi, WrLo, 0,  0, tid);
    stage_w_async(su, WrHi, WrLo, 64, 1, tid);
    stage_A_f32(smem, h, rowBase, M, tid);
    asm volatile("cp.async.wait_group 0;" ::: "memory");
    __syncthreads();
    mma_chunk(acc, 0, aHiB, aLoB, w0Hi, w0Lo);
    mma_chunk(acc, 4, aHiB, aLoB, w1Hi, w1Lo);

    int r0 = rowBase + wm * 16 + (lane >> 2);
#pragma unroll
    for (int c = 0; c < 2; c++)
#pragma unroll
        for (int p = 0; p < 2; p++)
#pragma unroll
            for (int t = 0; t < 2; t++) {
                float* A = acc[c * 4 + p * 2 + t];
                int col = c * 64 + wn * 32 + p * 16 + t * 8 + 2 * (lane & 3);
                if (r0 < M)     *((float2*)&P[(size_t)r0 * NF + col])       = make_float2(A[0], A[1]);
                if (r0 + 8 < M) *((float2*)&P[(size_t)(r0 + 8) * NF + col]) = make_float2(A[2], A[3]);
            }
}

// C = leaky(aggP @ Wl^T + partial + bias); 1 barrier
__global__ __launch_bounds__(256, 2) void gemmWl_kernel(
    const uint32_t* __restrict__ aggP,
    const uint16_t* __restrict__ WlHi, const uint16_t* __restrict__ WlLo,
    const float* __restrict__ P, const float* __restrict__ bias,
    float* __restrict__ C, int M)
{
    extern __shared__ char smem[];
    uint32_t su = smem_u32(smem);
    int tid = threadIdx.x, lane = tid & 31, wid = tid >> 5;
    int wm = wid & 3, wn = wid >> 2;
    int rowBase = blockIdx.x * 64;

    int lr = lane & 7, g = lane >> 3;
    uint32_t aOff = (uint32_t)((wm * 16 + lr + (g & 1) * 8) * A_STRIDE + (g >> 1) * 16);
    uint32_t bOff = (uint32_t)((wn * 32 + lr + (g >> 1) * 8) * A_STRIDE + (g & 1) * 16);
    uint32_t aHiB = su + SA_HI + aOff, aLoB = su + SA_LO + aOff;
    uint32_t w0Hi = su + SW_BASE + bOff,          w0Lo = w0Hi + 17408;
    uint32_t w1Hi = su + SW_BASE + SW_BUF + bOff, w1Lo = w1Hi + 17408;

    float acc[8][4];
#pragma unroll
    for (int i = 0; i < 8; i++)
#pragma unroll
        for (int q = 0; q < 4; q++) acc[i][q] = 0.f;

    stage_w_async(su, WlHi, WlLo, 0,  0, tid);
    stage_w_async(su, WlHi, WlLo, 64, 1, tid);
    stage_A_packed(smem, aggP, rowBase, M, tid);
    asm volatile("cp.async.wait_group 0;" ::: "memory");
    __syncthreads();
    mma_chunk(acc, 0, aHiB, aLoB, w0Hi, w0Lo);
    mma_chunk(acc, 4, aHiB, aLoB, w1Hi, w1Lo);

    int r0 = rowBase + wm * 16 + (lane >> 2);
#pragma unroll
    for (int c = 0; c < 2; c++)
#pragma unroll
        for (int p = 0; p < 2; p++)
#pragma unroll
            for (int t = 0; t < 2; t++) {
                float* A = acc[c * 4 + p * 2 + t];
                int col = c * 64 + wn * 32 + p * 16 + t * 8 + 2 * (lane & 3);
                float b0 = bias[col], b1 = bias[col + 1];
                if (r0 < M) {
                    float2 pr = *((const float2*)&P[(size_t)r0 * NF + col]);
                    float v0 = A[0] + pr.x + b0;
                    float v1 = A[1] + pr.y + b1;
                    v0 = (v0 >= 0.f) ? v0 : SLOPE * v0;
                    v1 = (v1 >= 0.f) ? v1 : SLOPE * v1;
                    *((float2*)&C[(size_t)r0 * NF + col]) = make_float2(v0, v1);
                }
                if (r0 + 8 < M) {
                    float2 pr = *((const float2*)&P[(size_t)(r0 + 8) * NF + col]);
                    float v2 = A[2] + pr.x + b0;
                    float v3 = A[3] + pr.y + b1;
                    v2 = (v2 >= 0.f) ? v2 : SLOPE * v2;
                    v3 = (v3 >= 0.f) ? v3 : SLOPE * v3;
                    *((float2*)&C[(size_t)(r0 + 8) * NF + col]) = make_float2(v2, v3);
                }
            }
}

// ---------------- fused final layer: gather + output; zeroes counts for next call ----------------
__global__ __launch_bounds__(256) void aggout_kernel(
    const float* __restrict__ h,
    const float* __restrict__ Wl, const float* __restrict__ bl,
    const float* __restrict__ Wr, float* __restrict__ out)
{
    int warp = (blockIdx.x * blockDim.x + threadIdx.x) >> 5;
    int lane = threadIdx.x & 31;
    if (warp >= NN) return;
    int cnt = g_counts[warp];
    const int* col = &g_col[warp * CAP];
    const float4* h4 = (const float4*)h;
    float4 m = make_float4(-FLT_MAX, -FLT_MAX, -FLT_MAX, -FLT_MAX);
    int e = 0;
    for (; e + 8 <= cnt; e += 8) {
        float4 v0 = h4[col[e]     * 32 + lane];
        float4 v1 = h4[col[e + 1] * 32 + lane];
        float4 v2 = h4[col[e + 2] * 32 + lane];
        float4 v3 = h4[col[e + 3] * 32 + lane];
        float4 v4 = h4[col[e + 4] * 32 + lane];
        float4 v5 = h4[col[e + 5] * 32 + lane];
        float4 v6 = h4[col[e + 6] * 32 + lane];
        float4 v7 = h4[col[e + 7] * 32 + lane];
        m = fmax4(m, fmax4(fmax4(fmax4(v0, v1), fmax4(v2, v3)),
                           fmax4(fmax4(v4, v5), fmax4(v6, v7))));
    }
    for (; e < cnt; e++) m = fmax4(m, h4[col[e] * 32 + lane]);
    if (cnt == 0) m = make_float4(0.f, 0.f, 0.f, 0.f);

    float4 hv = h4[warp * 32 + lane];
#pragma unroll
    for (int o = 0; o < 3; o++) {
        float4 wl = ((const float4*)Wl)[o * 32 + lane];
        float4 wr = ((const float4*)Wr)[o * 32 + lane];
        float s = m.x * wl.x + m.y * wl.y + m.z * wl.z + m.w * wl.w
                + hv.x * wr.x + hv.y * wr.y + hv.z * wr.z + hv.w * wr.w;
#pragma unroll
        for (int off = 16; off; off >>= 1)
            s += __shfl_xor_sync(0xffffffff, s, off);
        if (lane == 0) out[warp * 3 + o] = tanhf(s + bl[o]) * 0.5f;
    }
    if (lane == 0) g_counts[warp] = 0;
}

// ---------------- host launcher ----------------
extern "C" void kernel_launch(void* const* d_in, const int* in_sizes, int n_in,
                              void* d_out, int out_size)
{
    const float* x      = (const float*)d_in[0];
    const int*   ei     = (const int*)d_in[1];
    const float* Wl     = (const float*)d_in[2];
    const float* bl     = (const float*)d_in[3];
    const float* Wr     = (const float*)d_in[4];
    const float* Wl_out = (const float*)d_in[5];
    const float* bl_out = (const float*)d_in[6];
    const float* Wr_out = (const float*)d_in[7];
    float* out = (float*)d_out;

    const int* src = ei;
    const int* dst = ei + NE;

    void *pH0, *pH1, *pPar, *pAggP, *pWlHi, *pWlLo, *pWrHi, *pWrLo;
    cudaGetSymbolAddress(&pH0, g_h0);
    cudaGetSymbolAddress(&pH1, g_h1);
    cudaGetSymbolAddress(&pPar, g_partial);
    cudaGetSymbolAddress(&pAggP, g_aggP);
    cudaGetSymbolAddress(&pWlHi, g_WlHi);
    cudaGetSymbolAddress(&pWlLo, g_WlLo);
    cudaGetSymbolAddress(&pWrHi, g_WrHi);
    cudaGetSymbolAddress(&pWrLo, g_WrLo);
    float* h0  = (float*)pH0;
    float* h1  = (float*)pH1;
    float* par = (float*)pPar;
    uint32_t* aggP = (uint32_t*)pAggP;
    uint16_t* wlHi = (uint16_t*)pWlHi;
    uint16_t* wlLo = (uint16_t*)pWlLo;
    uint16_t* wrHi = (uint16_t*)pWrHi;
    uint16_t* wrLo = (uint16_t*)pWrLo;

    cudaFuncSetAttribute(gemmWr_kernel, cudaFuncAttributeMaxDynamicSharedMemorySize, SM_TOT);
    cudaFuncSetAttribute(gemmWl_kernel, cudaFuncAttributeMaxDynamicSharedMemorySize, SM_TOT);

    // lazy-once explicit streams + events (host/driver objects, no device alloc).
    // ALL kernels go on non-legacy streams so the captured graph keeps branches parallel.
    static cudaStream_t sA = nullptr, sB = nullptr;
    static cudaEvent_t evRoot = nullptr, evA = nullptr, evB = nullptr, evFill = nullptr, evDone = nullptr;
    if (sA == nullptr) {
        cudaStreamCreateWithFlags(&sA, cudaStreamNonBlocking);
        cudaStreamCreateWithFlags(&sB, cudaStreamNonBlocking);
        cudaEventCreateWithFlags(&evRoot, cudaEventDisableTiming);
        cudaEventCreateWithFlags(&evA, cudaEventDisableTiming);
        cudaEventCreateWithFlags(&evB, cudaEventDisableTiming);
        cudaEventCreateWithFlags(&evFill, cudaEventDisableTiming);
        cudaEventCreateWithFlags(&evDone, cudaEventDisableTiming);
    }

    const int AGG_BLOCKS  = (NN + 7) / 8;
    const int GEMM_BLOCKS = (NN + 63) / 64;

    // fork from the captured origin stream
    cudaEventRecord(evRoot, 0);
    cudaStreamWaitEvent(sA, evRoot, 0);
    cudaStreamWaitEvent(sB, evRoot, 0);

    // bucket CSR fill + weight pre-split on sA; sB needs the split weights
    fill_kernel<<<(NE + 255) / 256, 256, 0, sA>>>(src, dst, Wl, Wr);
    cudaEventRecord(evFill, sA);
    cudaStreamWaitEvent(sB, evFill, 0);

    const float* cur = x;
    for (int i = 0; i < NL; i++) {
        // sB: partial = cur @ Wr^T (overlaps agg on sA)
        gemmWr_kernel<<<GEMM_BLOCKS, 256, SM_TOT, sB>>>(
            cur, wrHi + (size_t)i * NF * NF, wrLo + (size_t)i * NF * NF, par, NN);
        cudaEventRecord(evB, sB);

        // sA: aggP = packed segment_max(cur)
        agg_kernel<<<AGG_BLOCKS, 256, 0, sA>>>(cur, aggP);

        // join, then C = leaky(aggP @ Wl^T + partial + bias) on sA
        cudaStreamWaitEvent(sA, evB, 0);
        float* nxt = (i & 1) ? h1 : h0;
        gemmWl_kernel<<<GEMM_BLOCKS, 256, SM_TOT, sA>>>(
            aggP, wlHi + (size_t)i * NF * NF, wlLo + (size_t)i * NF * NF,
            par, bl + i * NF, nxt, NN);
        cudaEventRecord(evA, sA);
        cudaStreamWaitEvent(sB, evA, 0);     // next gemmWr consumes nxt
        cur = nxt;
    }

    // fused final aggregation + output conv (+ counts reset) on sA
    aggout_kernel<<<AGG_BLOCKS, 256, 0, sA>>>(cur, Wl_out, bl_out, Wr_out, out);

    // join both branches back to the origin stream
    cudaEventRecord(evDone, sA);
    cudaStreamWaitEvent(0, evDone, 0);
    cudaEventRecord(evB, sB);
    cudaStreamWaitEvent(0, evB, 0);
}

// round 16
// speedup vs baseline: 1.2602x; 1.2602x over previous
#include <cuda_runtime.h>
#include <cuda_bf16.h>
#include <math.h>
#include <float.h>
#include <stdint.h>

// Problem constants (match reference)
#define NN 100000
#define NE 1600000
#define NF 128
#define NL 7
#define SLOPE 0.02f
#define CAP 64            // bucket capacity per node; P(deg>64)~1e-18 for Poisson(16)
#define NT 3125           // 100000 / 32 M-tiles, exact

// ---------------- device scratch (static, no allocation) ----------------
// g_counts zero-init at load; aggout re-zeroes it at the end of every call.
__device__ int g_counts[NN];
__device__ int g_col[NN * CAP];
__device__ __align__(16) float g_h0[NN * NF];
__device__ __align__(16) float g_h1[NN * NF];
__device__ __align__(16) uint32_t g_aggP[NN * NF];   // packed (bf16hi<<16)|bf16lo
// pre-split weights: hi/lo bf16, layout [l][n][k]
__device__ __align__(16) uint16_t g_WlHi[NL * NF * NF];
__device__ __align__(16) uint16_t g_WlLo[NL * NF * NF];
__device__ __align__(16) uint16_t g_WrHi[NL * NF * NF];
__device__ __align__(16) uint16_t g_WrLo[NL * NF * NF];

// ---------------- bucket CSR fill + weight pre-split (single launch) ----------------
__global__ void fill_kernel(const int* __restrict__ src, const int* __restrict__ dst,
                            const float* __restrict__ Wl, const float* __restrict__ Wr) {
    int e = blockIdx.x * blockDim.x + threadIdx.x;
    if (e < NE) {
        int d = dst[e];
        int off = atomicAdd(&g_counts[d], 1);
        g_col[d * CAP + off] = src[e];
    }
    if (e < NL * NF * NF) {
        float a = Wl[e];
        __nv_bfloat16 h = __float2bfloat16(a);
        g_WlHi[e] = __bfloat16_as_ushort(h);
        g_WlLo[e] = __bfloat16_as_ushort(__float2bfloat16(a - __bfloat162float(h)));
        float b = Wr[e];
        __nv_bfloat16 hb = __float2bfloat16(b);
        g_WrHi[e] = __bfloat16_as_ushort(hb);
        g_WrLo[e] = __bfloat16_as_ushort(__float2bfloat16(b - __bfloat162float(hb)));
    }
}

// ---------------- helpers ----------------
__device__ __forceinline__ float4 fmax4(float4 a, float4 b) {
    a.x = fmaxf(a.x, b.x); a.y = fmaxf(a.y, b.y);
    a.z = fmaxf(a.z, b.z); a.w = fmaxf(a.w, b.w);
    return a;
}

__device__ __forceinline__ uint32_t smem_u32(const void* p) {
    uint32_t a;
    asm("{ .reg .u64 t; cvta.to.shared.u64 t, %1; cvt.u32.u64 %0, t; }" : "=r"(a) : "l"(p));
    return a;
}

__device__ __forceinline__ void ldm4(uint32_t* r, uint32_t addr) {
    asm volatile("ldmatrix.sync.aligned.m8n8.x4.shared.b16 {%0,%1,%2,%3}, [%4];"
                 : "=r"(r[0]), "=r"(r[1]), "=r"(r[2]), "=r"(r[3]) : "r"(addr));
}

__device__ __forceinline__ void mma_bf16(float* d, const uint32_t* a, uint32_t b0, uint32_t b1) {
    asm volatile(
        "mma.sync.aligned.m16n8k16.row.col.f32.bf16.bf16.f32 "
        "{%0,%1,%2,%3}, {%4,%5,%6,%7}, {%8,%9}, {%0,%1,%2,%3};"
        : "+f"(d[0]), "+f"(d[1]), "+f"(d[2]), "+f"(d[3])
        : "r"(a[0]), "r"(a[1]), "r"(a[2]), "r"(a[3]), "r"(b0), "r"(b1));
}

__device__ __forceinline__ void cp16(uint32_t d, const void* s) {
    asm volatile("cp.async.cg.shared.global [%0], [%1], 16;" :: "r"(d), "l"(s));
}

// pack fp32 -> (bf16hi<<16)|bf16lo
__device__ __forceinline__ uint32_t pack1(float v) {
    __nv_bfloat16 h = __float2bfloat16(v);
    __nv_bfloat16 l = __float2bfloat16(v - __bfloat162float(h));
    return ((uint32_t)__bfloat16_as_ushort(h) << 16) | __bfloat16_as_ushort(l);
}

// ---------------- max aggregation: fp32 gather from buckets, packed output ----------------
__global__ __launch_bounds__(256) void agg_kernel(const float* __restrict__ h,
                                                  uint32_t* __restrict__ aggP) {
    int warp = (blockIdx.x * blockDim.x + threadIdx.x) >> 5;
    int lane = threadIdx.x & 31;
    if (warp >= NN) return;
    int cnt = g_counts[warp];
    const int* col = &g_col[warp * CAP];
    const float4* h4 = (const float4*)h;
    float4 m = make_float4(-FLT_MAX, -FLT_MAX, -FLT_MAX, -FLT_MAX);
    int e = 0;
    for (; e + 8 <= cnt; e += 8) {
        float4 v0 = h4[col[e]     * 32 + lane];
        float4 v1 = h4[col[e + 1] * 32 + lane];
        float4 v2 = h4[col[e + 2] * 32 + lane];
        float4 v3 = h4[col[e + 3] * 32 + lane];
        float4 v4 = h4[col[e + 4] * 32 + lane];
        float4 v5 = h4[col[e + 5] * 32 + lane];
        float4 v6 = h4[col[e + 6] * 32 + lane];
        float4 v7 = h4[col[e + 7] * 32 + lane];
        m = fmax4(m, fmax4(fmax4(fmax4(v0, v1), fmax4(v2, v3)),
                           fmax4(fmax4(v4, v5), fmax4(v6, v7))));
    }
    for (; e < cnt; e++) m = fmax4(m, h4[col[e] * 32 + lane]);
    if (cnt == 0) m = make_float4(0.f, 0.f, 0.f, 0.f);
    uint4 pk = make_uint4(pack1(m.x), pack1(m.y), pack1(m.z), pack1(m.w));
    ((uint4*)aggP)[warp * 32 + lane] = pk;
}

// ========== persistent bf16x3 dual GEMM: W resident, M=32 tiles, pipelined A ==========
#define A_STRIDE 272
#define W_PLANE  34816                 // 128 n-rows * 272
#define A_PLANE  8704                  // 32 rows * 272
#define A_BASE   (4 * W_PLANE)         // 139264
#define A_BUF    (4 * A_PLANE)         // 34816 per buffer (aggHi, aggLo, hHi, hLo)
#define SM_TOT   (A_BASE + 2 * A_BUF)  // 208896

// load registers for tile row0 (32 rows): 4 packed uint4 + 4 fp32 float4 per thread
__device__ __forceinline__ void ldA(const uint4* __restrict__ aggP4,
                                    const float4* __restrict__ h4,
                                    int row0, int tid, uint4 pk[4], float4 hv[4]) {
#pragma unroll
    for (int i = 0; i < 4; i++) {
        int idx = tid + i * 256;        // 0..1023
        int row = idx >> 5;             // 0..31
        int q   = idx & 31;
        pk[i] = aggP4[(size_t)(row0 + row) * 32 + q];
        hv[i] = h4[(size_t)(row0 + row) * 32 + q];
    }
}

// convert + store the loaded tile into A buffer `abase` (smem offset)
__device__ __forceinline__ void stA(char* smem, uint32_t abase, int tid,
                                    const uint4 pk[4], const float4 hv[4]) {
#pragma unroll
    for (int i = 0; i < 4; i++) {
        int idx = tid + i * 256;
        int row = idx >> 5;
        int q   = idx & 31;
        uint32_t off = (uint32_t)(row * A_STRIDE + q * 8);
        // packed agg -> planes 0,1
        uint4 p = pk[i];
        *(uint2*)(smem + abase + off) =
            make_uint2(__byte_perm(p.x, p.y, 0x7632), __byte_perm(p.z, p.w, 0x7632));
        *(uint2*)(smem + abase + A_PLANE + off) =
            make_uint2(__byte_perm(p.x, p.y, 0x5410), __byte_perm(p.z, p.w, 0x5410));
        // fp32 h -> planes 2,3
        float4 v = hv[i];
        __nv_bfloat16 hx = __float2bfloat16(v.x);
        __nv_bfloat16 hy = __float2bfloat16(v.y);
        __nv_bfloat16 hz = __float2bfloat16(v.z);
        __nv_bfloat16 hw = __float2bfloat16(v.w);
        uint32_t hi01 = ((uint32_t)__bfloat16_as_ushort(hy) << 16) | __bfloat16_as_ushort(hx);
        uint32_t hi23 = ((uint32_t)__bfloat16_as_ushort(hw) << 16) | __bfloat16_as_ushort(hz);
        __nv_bfloat16 lx = __float2bfloat16(v.x - __bfloat162float(hx));
        __nv_bfloat16 ly = __float2bfloat16(v.y - __bfloat162float(hy));
        __nv_bfloat16 lz = __float2bfloat16(v.z - __bfloat162float(hz));
        __nv_bfloat16 lw = __float2bfloat16(v.w - __bfloat162float(hw));
        uint32_t lo01 = ((uint32_t)__bfloat16_as_ushort(ly) << 16) | __bfloat16_as_ushort(lx);
        uint32_t lo23 = ((uint32_t)__bfloat16_as_ushort(lw) << 16) | __bfloat16_as_ushort(lz);
        *(uint2*)(smem + abase + 2 * A_PLANE + off) = make_uint2(hi01, hi23);
        *(uint2*)(smem + abase + 3 * A_PLANE + off) = make_uint2(lo01, lo23);
    }
}

// one half: acc += A(16rx128k from aHi/aLo) @ W^T(32 cols at bHi/bLo); 4 interleaved chains
__device__ __forceinline__ void mma_half(float acc[4][4],
                                         uint32_t aHiB, uint32_t aLoB,
                                         uint32_t bHiB, uint32_t bLoB) {
#pragma unroll
    for (int ks = 0; ks < 8; ks++) {
        uint32_t ko = ks * 32;
        uint32_t ah[4], al[4], b0h[4], b0l[4], b1h[4], b1l[4];
        ldm4(ah, aHiB + ko);
        ldm4(al, aLoB + ko);
        ldm4(b0h, bHiB + ko);
        ldm4(b0l, bLoB + ko);
        ldm4(b1h, bHiB + (uint32_t)(16 * A_STRIDE) + ko);
        ldm4(b1l, bLoB + (uint32_t)(16 * A_STRIDE) + ko);
        // 12 HMMA interleaved over 4 chains
        mma_bf16(acc[0], ah, b0h[0], b0h[1]);
        mma_bf16(acc[1], ah, b0h[2], b0h[3]);
        mma_bf16(acc[2], ah, b1h[0], b1h[1]);
        mma_bf16(acc[3], ah, b1h[2], b1h[3]);
        mma_bf16(acc[0], ah, b0l[0], b0l[1]);
        mma_bf16(acc[1], ah, b0l[2], b0l[3]);
        mma_bf16(acc[2], ah, b1l[0], b1l[1]);
        mma_bf16(acc[3], ah, b1l[2], b1l[3]);
        mma_bf16(acc[0], al, b0h[0], b0h[1]);
        mma_bf16(acc[1], al, b0h[2], b0h[3]);
        mma_bf16(acc[2], al, b1h[0], b1h[1]);
        mma_bf16(acc[3], al, b1h[2], b1h[3]);
    }
}

__global__ __launch_bounds__(256, 1) void gemm_kernel(
    const uint32_t* __restrict__ aggP, const float* __restrict__ h,
    const uint16_t* __restrict__ WlHi, const uint16_t* __restrict__ WlLo,
    const uint16_t* __restrict__ WrHi, const uint16_t* __restrict__ WrLo,
    const float* __restrict__ bias, float* __restrict__ C)
{
    extern __shared__ char smem[];
    uint32_t su = smem_u32(smem);
    int tid = threadIdx.x;
    int lane = tid & 31;
    int wid = tid >> 5;
    int wm = wid & 1;        // 2 M-groups x 16 rows
    int wn = wid >> 1;       // 4 N-groups x 32 cols

    // ---- prologue: load all 4 W planes (resident for the whole kernel) ----
    {
        const uint16_t* srcs[4] = {WlHi, WlLo, WrHi, WrLo};
#pragma unroll
        for (int i = 0; i < 32; i++) {
            int idx = tid + i * 256;        // 0..8191
            int plane = idx >> 11;
            int rem = idx & 2047;
            int nl = rem >> 4;              // 0..127
            int q  = rem & 15;
            uint32_t dst = su + plane * W_PLANE + nl * A_STRIDE + q * 16;
            cp16(dst, srcs[plane] + (size_t)nl * NF + q * 8);
        }
        asm volatile("cp.async.commit_group;" ::: "memory");
    }

    // per-lane ldmatrix bases
    int lr = lane & 7, g = lane >> 3;
    uint32_t aOff = (uint32_t)((wm * 16 + lr + (g & 1) * 8) * A_STRIDE + (g >> 1) * 16);
    uint32_t bOff = (uint32_t)((wn * 32 + lr + (g >> 1) * 8) * A_STRIDE + (g & 1) * 16);
    uint32_t wlHiB = su + 0 * W_PLANE + bOff, wlLoB = su + 1 * W_PLANE + bOff;
    uint32_t wrHiB = su + 2 * W_PLANE + bOff, wrLoB = su + 3 * W_PLANE + bOff;

    // bias registers (columns fixed per warp across tiles)
    float bs0[4], bs1[4];
#pragma unroll
    for (int c = 0; c < 4; c++) {
        int col = wn * 32 + (c >> 1) * 16 + (c & 1) * 8 + 2 * (lane & 3);
        bs0[c] = bias[col];
        bs1[c] = bias[col + 1];
    }

    const uint4*  aggP4 = (const uint4*)aggP;
    const float4* h4    = (const float4*)h;

    int t = blockIdx.x;
    int G = gridDim.x;

    // stage tile t into buffer 0
    uint4 pk[4]; float4 hv[4];
    ldA(aggP4, h4, t * 32, tid, pk, hv);
    asm volatile("cp.async.wait_group 0;" ::: "memory");
    stA(smem, A_BASE, tid, pk, hv);
    __syncthreads();

    int buf = 0;
    for (; t < NT; t += G) {
        int tn = t + G;
        if (tn < NT) ldA(aggP4, h4, tn * 32, tid, pk, hv);   // loads in flight under mma

        uint32_t ab = su + A_BASE + buf * A_BUF;
        float acc[4][4];
#pragma unroll
        for (int i = 0; i < 4; i++)
#pragma unroll
            for (int q = 0; q < 4; q++) acc[i][q] = 0.f;

        mma_half(acc, ab + aOff, ab + A_PLANE + aOff, wlHiB, wlLoB);                 // agg @ Wl
        mma_half(acc, ab + 2 * A_PLANE + aOff, ab + 3 * A_PLANE + aOff, wrHiB, wrLoB); // h @ Wr

        // epilogue: bias + leaky, fp32 stores (rows always in range: NT*32 == NN)
        int r0 = t * 32 + wm * 16 + (lane >> 2);
#pragma unroll
        for (int c = 0; c < 4; c++) {
            int col = wn * 32 + (c >> 1) * 16 + (c & 1) * 8 + 2 * (lane & 3);
            float v0 = acc[c][0] + bs0[c];
            float v1 = acc[c][1] + bs1[c];
            float v2 = acc[c][2] + bs0[c];
            float v3 = acc[c][3] + bs1[c];
            v0 = (v0 >= 0.f) ? v0 : SLOPE * v0;
            v1 = (v1 >= 0.f) ? v1 : SLOPE * v1;
            v2 = (v2 >= 0.f) ? v2 : SLOPE * v2;
            v3 = (v3 >= 0.f) ? v3 : SLOPE * v3;
            *((float2*)&C[(size_t)r0 * NF + col])       = make_float2(v0, v1);
            *((float2*)&C[(size_t)(r0 + 8) * NF + col]) = make_float2(v2, v3);
        }

        if (tn < NT) stA(smem, A_BASE + (buf ^ 1) * A_BUF, tid, pk, hv);
        __syncthreads();
        buf ^= 1;
    }
}

// ---------------- fused final layer: gather + output; zeroes counts for next call ----------------
__global__ __launch_bounds__(256) void aggout_kernel(
    const float* __restrict__ h,
    const float* __restrict__ Wl, const float* __restrict__ bl,
    const float* __restrict__ Wr, float* __restrict__ out)
{
    int warp = (blockIdx.x * blockDim.x + threadIdx.x) >> 5;
    int lane = threadIdx.x & 31;
    if (warp >= NN) return;
    int cnt = g_counts[warp];
    const int* col = &g_col[warp * CAP];
    const float4* h4 = (const float4*)h;
    float4 m = make_float4(-FLT_MAX, -FLT_MAX, -FLT_MAX, -FLT_MAX);
    int e = 0;
    for (; e + 8 <= cnt; e += 8) {
        float4 v0 = h4[col[e]     * 32 + lane];
        float4 v1 = h4[col[e + 1] * 32 + lane];
        float4 v2 = h4[col[e + 2] * 32 + lane];
        float4 v3 = h4[col[e + 3] * 32 + lane];
        float4 v4 = h4[col[e + 4] * 32 + lane];
        float4 v5 = h4[col[e + 5] * 32 + lane];
        float4 v6 = h4[col[e + 6] * 32 + lane];
        float4 v7 = h4[col[e + 7] * 32 + lane];
        m = fmax4(m, fmax4(fmax4(fmax4(v0, v1), fmax4(v2, v3)),
                           fmax4(fmax4(v4, v5), fmax4(v6, v7))));
    }
    for (; e < cnt; e++) m = fmax4(m, h4[col[e] * 32 + lane]);
    if (cnt == 0) m = make_float4(0.f, 0.f, 0.f, 0.f);

    float4 hv = h4[warp * 32 + lane];
#pragma unroll
    for (int o = 0; o < 3; o++) {
        float4 wl = ((const float4*)Wl)[o * 32 + lane];
        float4 wr = ((const float4*)Wr)[o * 32 + lane];
        float s = m.x * wl.x + m.y * wl.y + m.z * wl.z + m.w * wl.w
                + hv.x * wr.x + hv.y * wr.y + hv.z * wr.z + hv.w * wr.w;
#pragma unroll
        for (int off = 16; off; off >>= 1)
            s += __shfl_xor_sync(0xffffffff, s, off);
        if (lane == 0) out[warp * 3 + o] = tanhf(s + bl[o]) * 0.5f;
    }
    if (lane == 0) g_counts[warp] = 0;
}

// ---------------- host launcher ----------------
extern "C" void kernel_launch(void* const* d_in, const int* in_sizes, int n_in,
                              void* d_out, int out_size)
{
    const float* x      = (const float*)d_in[0];
    const int*   ei     = (const int*)d_in[1];
    const float* Wl     = (const float*)d_in[2];
    const float* bl     = (const float*)d_in[3];
    const float* Wr     = (const float*)d_in[4];
    const float* Wl_out = (const float*)d_in[5];
    const float* bl_out = (const float*)d_in[6];
    const float* Wr_out = (const float*)d_in[7];
    float* out = (float*)d_out;

    const int* src = ei;
    const int* dst = ei + NE;

    void *pH0, *pH1, *pAggP, *pWlHi, *pWlLo, *pWrHi, *pWrLo;
    cudaGetSymbolAddress(&pH0, g_h0);
    cudaGetSymbolAddress(&pH1, g_h1);
    cudaGetSymbolAddress(&pAggP, g_aggP);
    cudaGetSymbolAddress(&pWlHi, g_WlHi);
    cudaGetSymbolAddress(&pWlLo, g_WlLo);
    cudaGetSymbolAddress(&pWrHi, g_WrHi);
    cudaGetSymbolAddress(&pWrLo, g_WrLo);
    float* h0  = (float*)pH0;
    float* h1  = (float*)pH1;
    uint32_t* aggP = (uint32_t*)pAggP;
    uint16_t* wlHi = (uint16_t*)pWlHi;
    uint16_t* wlLo = (uint16_t*)pWlLo;
    uint16_t* wrHi = (uint16_t*)pWrHi;
    uint16_t* wrLo = (uint16_t*)pWrLo;

    static int s_sm = 0;
    if (s_sm == 0) {
        cudaDeviceGetAttribute(&s_sm, cudaDevAttrMultiProcessorCount, 0);
        if (s_sm <= 0) s_sm = 148;
        cudaFuncSetAttribute(gemm_kernel, cudaFuncAttributeMaxDynamicSharedMemorySize, SM_TOT);
    }

    // bucket CSR fill + weight pre-split (counts zeroed by previous call's aggout)
    fill_kernel<<<(NE + 255) / 256, 256>>>(src, dst, Wl, Wr);

    const int AGG_BLOCKS = (NN + 7) / 8;
    int GEMM_BLOCKS = s_sm;
    if (GEMM_BLOCKS > NT) GEMM_BLOCKS = NT;

    const float* cur = x;
    for (int i = 0; i < NL; i++) {
        agg_kernel<<<AGG_BLOCKS, 256>>>(cur, aggP);
        float* nxt = (i & 1) ? h1 : h0;
        gemm_kernel<<<GEMM_BLOCKS, 256, SM_TOT>>>(
            aggP, cur,
            wlHi + (size_t)i * NF * NF, wlLo + (size_t)i * NF * NF,
            wrHi + (size_t)i * NF * NF, wrLo + (size_t)i * NF * NF,
            bl + i * NF, nxt);
        cur = nxt;
    }

    // fused final aggregation + output conv (+ counts reset)
    aggout_kernel<<<AGG_BLOCKS, 256>>>(cur, Wl_out, bl_out, Wr_out, out);
}